// round 4
// baseline (speedup 1.0000x reference)
#include <cuda_runtime.h>

#define THREADS 256
#define WARPS (THREADS / 32)
#define SUBHISTS (WARPS * 2)   // per-warp even/odd lane split
#define BINS 256
#define NBLOCKS (148 * 8)

// Zero-initialized device scratch. Each kernel call leaves these re-zeroed
// (last block resets them), so every graph replay sees the same initial state.
__device__ unsigned int g_partial[BINS];
__device__ unsigned int g_ticket;

__device__ __forceinline__ void bin_one(float f, unsigned int* hw) {
    // torch.histc: bins over [-4,4], x==4 -> last bin, outside ignored.
    // (f+4)*32 == fmaf(f,32,128) bit-exactly (x32 is an exact binade shift).
    if (fabsf(f) <= 4.0f) {
        int b = __float2int_rd(fmaf(f, 32.0f, 128.0f));
        b = min(b, BINS - 1);
        atomicAdd(&hw[b], 1u);
    }
}

__device__ __forceinline__ void bin4(float4 v, unsigned int* hw) {
    bin_one(v.x, hw);
    bin_one(v.y, hw);
    bin_one(v.z, hw);
    bin_one(v.w, hw);
}

__global__ __launch_bounds__(THREADS) void histc_kernel(
    const float4* __restrict__ x, float* __restrict__ out, int n4, int dup)
{
    __shared__ unsigned int h[SUBHISTS][BINS];
    __shared__ bool is_last;

    unsigned int* hflat = &h[0][0];
    #pragma unroll
    for (int i = threadIdx.x; i < SUBHISTS * BINS; i += THREADS)
        hflat[i] = 0u;
    __syncthreads();

    // Sub-histogram per (warp, lane parity) to halve atomic conflicts.
    unsigned int* hw = h[((threadIdx.x >> 5) << 1) | (threadIdx.x & 1)];

    const int stride = gridDim.x * blockDim.x;
    int i = blockIdx.x * blockDim.x + threadIdx.x;

    // Unroll x4: four 16B streaming loads in flight before any binning.
    for (; i + 3 * stride < n4; i += 4 * stride) {
        float4 a = __ldcs(&x[i]);
        float4 b = __ldcs(&x[i + stride]);
        float4 c = __ldcs(&x[i + 2 * stride]);
        float4 d = __ldcs(&x[i + 3 * stride]);
        bin4(a, hw);
        bin4(b, hw);
        bin4(c, hw);
        bin4(d, hw);
    }
    for (; i < n4; i += stride) {
        float4 a = __ldcs(&x[i]);
        bin4(a, hw);
    }
    __syncthreads();

    // Block-level reduce of the 16 sub-histograms -> one global atomic per bin.
    {
        int b = threadIdx.x;
        unsigned int s = 0;
        #pragma unroll
        for (int w = 0; w < SUBHISTS; w++)
            s += h[w][b];
        if (s)
            atomicAdd(&g_partial[b], s);
    }

    // Last-block-done: the final block writes the outputs and resets scratch.
    __threadfence();
    if (threadIdx.x == 0) {
        unsigned int t = atomicAdd(&g_ticket, 1u);
        is_last = (t == (unsigned int)gridDim.x - 1u);
    }
    __syncthreads();

    if (is_last) {
        int b = threadIdx.x;
        // L2-coherent read of the final total (avoids any stale-L1 concern).
        unsigned int v = atomicAdd(&g_partial[b], 0u);
        float fv = (float)v;
        out[b] = fv;            // plain store overwrites harness poison
        if (dup)
            out[b + BINS] = fv;
        g_partial[b] = 0u;      // re-zero scratch for the next graph replay
        if (b == 0)
            g_ticket = 0u;
    }
}

extern "C" void kernel_launch(void* const* d_in, const int* in_sizes, int n_in,
                              void* d_out, int out_size)
{
    const float4* x = (const float4*)d_in[0];
    float* out = (float*)d_out;
    int n4 = in_sizes[0] / 4;
    int dup = (out_size >= 2 * BINS) ? 1 : 0;

    histc_kernel<<<NBLOCKS, THREADS>>>(x, out, n4, dup);
}

// round 5
// speedup vs baseline: 1.3843x; 1.3843x over previous
#include <cuda_runtime.h>

#define THREADS 256
#define WARPS (THREADS / 32)
#define SUBHISTS (WARPS * 2)   // per-warp even/odd lane split
#define BINS 256
#define NBLOCKS (148 * 8)

// Zero-initialized device scratch. The last block re-zeroes it every call, so
// every graph replay sees identical initial state (deterministic).
__device__ unsigned int g_partial[BINS];
__device__ unsigned int g_ticket;

__device__ __forceinline__ void bin_one(float f, unsigned int* hw) {
    // torch.histc: bins over [-4,4], x==4 -> last bin, outside ignored.
    // (f+4)*32 == fmaf(f,32,128) bit-exactly (x32 is an exact binade shift).
    if (fabsf(f) <= 4.0f) {
        int b = __float2int_rd(fmaf(f, 32.0f, 128.0f));
        b = min(b, BINS - 1);
        atomicAdd(&hw[b], 1u);
    }
}

__device__ __forceinline__ void bin4(float4 v, unsigned int* hw) {
    bin_one(v.x, hw);
    bin_one(v.y, hw);
    bin_one(v.z, hw);
    bin_one(v.w, hw);
}

__global__ __launch_bounds__(THREADS) void histc_kernel(
    const float4* __restrict__ x, float* __restrict__ out, int n4, int dup)
{
    __shared__ unsigned int h[SUBHISTS][BINS];
    __shared__ bool is_last;

    unsigned int* hflat = &h[0][0];
    #pragma unroll
    for (int i = threadIdx.x; i < SUBHISTS * BINS; i += THREADS)
        hflat[i] = 0u;
    __syncthreads();

    // Sub-histogram per (warp, lane parity).
    unsigned int* hw = h[((threadIdx.x >> 5) << 1) | (threadIdx.x & 1)];

    const int stride = gridDim.x * blockDim.x;
    int i = blockIdx.x * blockDim.x + threadIdx.x;

    // Unroll x2 ONLY: MLP_p1=2 is the measured sweet spot — x4 overflows the
    // per-SM L1tex wavefront queue at occ=8 (R4 regression, 67us vs 49us).
    for (; i + stride < n4; i += 2 * stride) {
        float4 a = __ldcs(&x[i]);
        float4 b = __ldcs(&x[i + stride]);
        bin4(a, hw);
        bin4(b, hw);
    }
    if (i < n4) {
        float4 a = __ldcs(&x[i]);
        bin4(a, hw);
    }
    __syncthreads();

    // Block-level reduce of the 16 sub-histograms -> one global atomic per bin.
    {
        int b = threadIdx.x;
        unsigned int s = 0;
        #pragma unroll
        for (int w = 0; w < SUBHISTS; w++)
            s += h[w][b];
        if (s)
            atomicAdd(&g_partial[b], s);
    }

    // Last-block-done epilogue: final block writes both output copies and
    // resets scratch. Plain stores overwrite the harness poison.
    __threadfence();
    if (threadIdx.x == 0) {
        unsigned int t = atomicAdd(&g_ticket, 1u);
        is_last = (t == (unsigned int)gridDim.x - 1u);
    }
    __syncthreads();

    if (is_last) {
        int b = threadIdx.x;
        unsigned int v = atomicAdd(&g_partial[b], 0u);  // L2-coherent read
        float fv = (float)v;
        out[b] = fv;
        if (dup)
            out[b + BINS] = fv;
        g_partial[b] = 0u;      // reset for next graph replay
        if (b == 0)
            g_ticket = 0u;
    }
}

extern "C" void kernel_launch(void* const* d_in, const int* in_sizes, int n_in,
                              void* d_out, int out_size)
{
    const float4* x = (const float4*)d_in[0];
    float* out = (float*)d_out;
    int n4 = in_sizes[0] / 4;
    int dup = (out_size >= 2 * BINS) ? 1 : 0;

    histc_kernel<<<NBLOCKS, THREADS>>>(x, out, n4, dup);
}

// round 6
// speedup vs baseline: 1.3851x; 1.0006x over previous
#include <cuda_runtime.h>

#define THREADS 256
#define WARPS (THREADS / 32)
#define SUBHISTS (WARPS * 2)   // per-warp even/odd lane split
#define BINS 256
#define NBLOCKS (148 * 8)

// Zero-initialized device scratch. The last block re-zeroes it every call, so
// every graph replay sees identical initial state (deterministic).
__device__ unsigned int g_partial[BINS];
__device__ unsigned int g_ticket;

// Bank-decorrelating bijection: b ^ (b>>3) flips bank bits for any bin
// difference that is a multiple of 32, killing the Gaussian mod-32 aliasing
// on the smem crossbar. Invertible (upper-triangular over GF(2)).
__device__ __forceinline__ int swz(int b) { return b ^ (b >> 3); }

__device__ __forceinline__ void bin_one(float f, unsigned int* hw) {
    // torch.histc: bins over [-4,4], x==4 -> last bin, outside ignored.
    // (f+4)*32 == fmaf(f,32,128) bit-exactly (x32 is an exact binade shift).
    if (fabsf(f) <= 4.0f) {
        int b = __float2int_rd(fmaf(f, 32.0f, 128.0f));
        b = min(b, BINS - 1);
        atomicAdd(&hw[swz(b)], 1u);
    }
}

__device__ __forceinline__ void bin4(float4 v, unsigned int* hw) {
    bin_one(v.x, hw);
    bin_one(v.y, hw);
    bin_one(v.z, hw);
    bin_one(v.w, hw);
}

__global__ __launch_bounds__(THREADS) void histc_kernel(
    const float4* __restrict__ x, float* __restrict__ out, int n4, int dup)
{
    __shared__ unsigned int h[SUBHISTS][BINS];
    __shared__ bool is_last;

    unsigned int* hflat = &h[0][0];
    #pragma unroll
    for (int i = threadIdx.x; i < SUBHISTS * BINS; i += THREADS)
        hflat[i] = 0u;
    __syncthreads();

    // Sub-histogram per (warp, lane parity).
    unsigned int* hw = h[((threadIdx.x >> 5) << 1) | (threadIdx.x & 1)];

    const int stride = gridDim.x * blockDim.x;
    int i = blockIdx.x * blockDim.x + threadIdx.x;

    // Software-pipelined, MLP_p1=2 (R4 showed 4 consecutive front LDGs
    // overflows the L1tex wavefront queue at occ=8). Prefetch the next pair
    // before binning the current pair so load latency overlaps with binning.
    if (i + stride < n4) {
        float4 a = __ldcs(&x[i]);
        float4 b = __ldcs(&x[i + stride]);
        i += 2 * stride;
        for (; i + stride < n4; i += 2 * stride) {
            float4 na = __ldcs(&x[i]);
            float4 nb = __ldcs(&x[i + stride]);
            bin4(a, hw);
            bin4(b, hw);
            a = na;
            b = nb;
        }
        bin4(a, hw);
        bin4(b, hw);
    }
    for (; i < n4; i += stride) {          // tail: 0 or 1 leftover vectors
        float4 t = __ldcs(&x[i]);
        bin4(t, hw);
    }
    __syncthreads();

    // Block-level reduce (un-swizzle) -> one global atomic per bin.
    {
        int b = threadIdx.x;
        int sb = swz(b);
        unsigned int s = 0;
        #pragma unroll
        for (int w = 0; w < SUBHISTS; w++)
            s += h[w][sb];
        if (s)
            atomicAdd(&g_partial[b], s);
    }

    // Last-block-done epilogue: final block writes both output copies and
    // resets scratch. Plain stores overwrite the harness poison.
    __threadfence();
    if (threadIdx.x == 0) {
        unsigned int t = atomicAdd(&g_ticket, 1u);
        is_last = (t == (unsigned int)gridDim.x - 1u);
    }
    __syncthreads();

    if (is_last) {
        int b = threadIdx.x;
        unsigned int v = atomicAdd(&g_partial[b], 0u);  // L2-coherent read
        float fv = (float)v;
        out[b] = fv;
        if (dup)
            out[b + BINS] = fv;
        g_partial[b] = 0u;      // reset for next graph replay
        if (b == 0)
            g_ticket = 0u;
    }
}

extern "C" void kernel_launch(void* const* d_in, const int* in_sizes, int n_in,
                              void* d_out, int out_size)
{
    const float4* x = (const float4*)d_in[0];
    float* out = (float*)d_out;
    int n4 = in_sizes[0] / 4;
    int dup = (out_size >= 2 * BINS) ? 1 : 0;

    histc_kernel<<<NBLOCKS, THREADS>>>(x, out, n4, dup);
}

// round 7
// speedup vs baseline: 1.5166x; 1.0949x over previous
#include <cuda_runtime.h>

#define THREADS 512
#define BINS 256
#define NBLOCKS (148 * 4)   // 4 blocks/SM x 512 threads = 2048 threads/SM

// Zero-initialized device scratch. The last block re-zeroes it every call, so
// every graph replay sees identical initial state (deterministic).
__device__ unsigned int g_partial[BINS];
__device__ unsigned int g_ticket;

// Histogram layout h[bin][lane]: lane l only touches column l, so every
// warp-ATOMS hits 32 DISTINCT banks (bank = (b*32+l)%32 = l). Structurally
// conflict-free shared atomics — no bank conflicts, no intra-warp
// same-address serialization, ever.
__device__ __forceinline__ void bin_one(float f, unsigned int* hl) {
    // torch.histc: bins over [-4,4], x==4 -> last bin, outside ignored.
    // (f+4)*32 == fmaf(f,32,128) bit-exactly (x32 is an exact binade shift).
    if (fabsf(f) <= 4.0f) {
        int b = __float2int_rd(fmaf(f, 32.0f, 128.0f));
        b = min(b, BINS - 1);
        atomicAdd(&hl[b << 5], 1u);   // hl already offset by lane
    }
}

__device__ __forceinline__ void bin4(float4 v, unsigned int* hl) {
    bin_one(v.x, hl);
    bin_one(v.y, hl);
    bin_one(v.z, hl);
    bin_one(v.w, hl);
}

__global__ __launch_bounds__(THREADS) void histc_kernel(
    const float4* __restrict__ x, float* __restrict__ out, int n4, int dup)
{
    __shared__ unsigned int h[BINS * 32];   // 32 KB: h[b*32 + lane]
    __shared__ bool is_last;

    #pragma unroll
    for (int i = threadIdx.x; i < BINS * 32; i += THREADS)
        h[i] = 0u;
    __syncthreads();

    const int lane = threadIdx.x & 31;
    unsigned int* hl = &h[lane];

    const int stride = gridDim.x * blockDim.x;
    int i = blockIdx.x * blockDim.x + threadIdx.x;

    // Software-pipelined, MLP_p1=2 (x4 front-batching overflowed the L1tex
    // wavefront queue in R4). Prefetch the next pair while binning current.
    if (i + stride < n4) {
        float4 a = __ldcs(&x[i]);
        float4 b = __ldcs(&x[i + stride]);
        i += 2 * stride;
        for (; i + stride < n4; i += 2 * stride) {
            float4 na = __ldcs(&x[i]);
            float4 nb = __ldcs(&x[i + stride]);
            bin4(a, hl);
            bin4(b, hl);
            a = na;
            b = nb;
        }
        bin4(a, hl);
        bin4(b, hl);
    }
    for (; i < n4; i += stride) {
        float4 t = __ldcs(&x[i]);
        bin4(t, hl);
    }
    __syncthreads();

    // Reduce 32 lane-columns per bin. Diagonal read (start at own lane) keeps
    // all 32 lanes of a warp on distinct banks every step.
    if (threadIdx.x < BINS) {
        int b = threadIdx.x;
        unsigned int s = 0;
        #pragma unroll
        for (int k = 0; k < 32; k++)
            s += h[(b << 5) + ((k + lane) & 31)];
        if (s)
            atomicAdd(&g_partial[b], s);
    }

    // Last-block-done epilogue: final block writes both output copies and
    // resets scratch. Plain stores overwrite the harness poison.
    __threadfence();
    if (threadIdx.x == 0) {
        unsigned int t = atomicAdd(&g_ticket, 1u);
        is_last = (t == (unsigned int)gridDim.x - 1u);
    }
    __syncthreads();

    if (is_last && threadIdx.x < BINS) {
        int b = threadIdx.x;
        unsigned int v = atomicAdd(&g_partial[b], 0u);  // L2-coherent read
        float fv = (float)v;
        out[b] = fv;
        if (dup)
            out[b + BINS] = fv;
        g_partial[b] = 0u;      // reset for next graph replay
        if (b == 0)
            g_ticket = 0u;
    }
}

extern "C" void kernel_launch(void* const* d_in, const int* in_sizes, int n_in,
                              void* d_out, int out_size)
{
    const float4* x = (const float4*)d_in[0];
    float* out = (float*)d_out;
    int n4 = in_sizes[0] / 4;
    int dup = (out_size >= 2 * BINS) ? 1 : 0;

    histc_kernel<<<NBLOCKS, THREADS>>>(x, out, n4, dup);
}

// round 8
// speedup vs baseline: 1.5238x; 1.0048x over previous
#include <cuda_runtime.h>

#define THREADS 512
#define BINS 256
#define NBLOCKS (148 * 4)   // 4 blocks/SM x 512 threads = 2048 threads/SM

// Zero-initialized device scratch. The last block re-zeroes it every call, so
// every graph replay sees identical initial state (deterministic).
__device__ unsigned int g_partial[BINS];
__device__ unsigned int g_ticket;

// Histogram layout h[bin][lane]: lane l only touches column l, so every
// warp-ATOMS hits 32 DISTINCT banks. Structurally conflict-free shared
// atomics (proven R7: L1% 63->33, dur 51.7->47.2).
__device__ __forceinline__ void bin_one(float f, unsigned int* hl) {
    // torch.histc: bins over [-4,4], x==4 -> last bin, outside ignored.
    // (f+4)*32 == fmaf(f,32,128) bit-exactly (x32 is an exact binade shift).
    if (fabsf(f) <= 4.0f) {
        int b = __float2int_rd(fmaf(f, 32.0f, 128.0f));
        b = min(b, BINS - 1);
        atomicAdd(&hl[b << 5], 1u);   // hl already offset by lane
    }
}

__device__ __forceinline__ void bin4(float4 v, unsigned int* hl) {
    bin_one(v.x, hl);
    bin_one(v.y, hl);
    bin_one(v.z, hl);
    bin_one(v.w, hl);
}

__global__ __launch_bounds__(THREADS) void histc_kernel(
    const float4* __restrict__ x, float* __restrict__ out, int n4, int dup)
{
    __shared__ unsigned int h[BINS * 32];   // 32 KB: h[b*32 + lane]
    __shared__ bool is_last;

    #pragma unroll
    for (int i = threadIdx.x; i < BINS * 32; i += THREADS)
        h[i] = 0u;
    __syncthreads();

    const int lane = threadIdx.x & 31;
    unsigned int* hl = &h[lane];

    const int stride = gridDim.x * blockDim.x;
    int i = blockIdx.x * blockDim.x + threadIdx.x;

    // Depth-3 software pipeline: 3 x 16B in flight per thread.
    // oe*MLP_p1 = 4*3 = 12 < Q_th(16): inside the safe region of the
    // cross-CTA L1tex-queue model (R4 showed oe*MLP=32 regresses badly).
    if (i + 2 * stride < n4) {
        float4 a = __ldcs(&x[i]);
        float4 b = __ldcs(&x[i + stride]);
        float4 c = __ldcs(&x[i + 2 * stride]);
        i += 3 * stride;
        for (; i + 2 * stride < n4; i += 3 * stride) {
            float4 na = __ldcs(&x[i]);
            bin4(a, hl);
            float4 nb = __ldcs(&x[i + stride]);
            bin4(b, hl);
            float4 nc = __ldcs(&x[i + 2 * stride]);
            bin4(c, hl);
            a = na;
            b = nb;
            c = nc;
        }
        bin4(a, hl);
        bin4(b, hl);
        bin4(c, hl);
    }
    for (; i < n4; i += stride) {           // 0..2 leftover vectors
        float4 t = __ldcs(&x[i]);
        bin4(t, hl);
    }
    __syncthreads();

    // Reduce 32 lane-columns per bin. Diagonal read (start at own lane) keeps
    // all 32 lanes of a warp on distinct banks every step.
    if (threadIdx.x < BINS) {
        int b = threadIdx.x;
        unsigned int s = 0;
        #pragma unroll
        for (int k = 0; k < 32; k++)
            s += h[(b << 5) + ((k + lane) & 31)];
        if (s)
            atomicAdd(&g_partial[b], s);
    }

    // Last-block-done epilogue: final block writes both output copies and
    // resets scratch. Plain stores overwrite the harness poison.
    __threadfence();
    if (threadIdx.x == 0) {
        unsigned int t = atomicAdd(&g_ticket, 1u);
        is_last = (t == (unsigned int)gridDim.x - 1u);
    }
    __syncthreads();

    if (is_last && threadIdx.x < BINS) {
        int b = threadIdx.x;
        unsigned int v = atomicAdd(&g_partial[b], 0u);  // L2-coherent read
        float fv = (float)v;
        out[b] = fv;
        if (dup)
            out[b + BINS] = fv;
        g_partial[b] = 0u;      // reset for next graph replay
        if (b == 0)
            g_ticket = 0u;
    }
}

extern "C" void kernel_launch(void* const* d_in, const int* in_sizes, int n_in,
                              void* d_out, int out_size)
{
    const float4* x = (const float4*)d_in[0];
    float* out = (float*)d_out;
    int n4 = in_sizes[0] / 4;
    int dup = (out_size >= 2 * BINS) ? 1 : 0;

    histc_kernel<<<NBLOCKS, THREADS>>>(x, out, n4, dup);
}